// round 1
// baseline (speedup 1.0000x reference)
#include <cuda_runtime.h>

typedef unsigned long long ull;

#define D_DIM 11008
#define K_DIM 172
#define M_DIM 64
#define THREADS 512
#define JT 16          // had_K j-tile width
#define NT 11          // ceil(172/16)
#define TI 6           // output rows (i) per thread
#define TM 8           // output cols (m) per thread

// smem layout (floats):
//   xs  : 2*11008 data + 256 zero pad           = 22272
//   hkd : 2 double-buffers of duplicated had_K tile, stride 354 floats per jj,
//         buffer size 5696 floats each          = 11392
#define XS_FLOATS   22272
#define HK_BUF      5696
#define SMEM_FLOATS (XS_FLOATS + 2*HK_BUF)   // 33664 floats = 134656 B

static __device__ __forceinline__ ull fma2(ull a, ull b, ull c) {
    ull d;
    asm("fma.rn.f32x2 %0, %1, %2, %3;" : "=l"(d) : "l"(a), "l"(b), "l"(c));
    return d;
}

__global__ __launch_bounds__(THREADS, 1)
void had_fused_kernel(const float* __restrict__ x,
                      const float* __restrict__ hK,
                      float* __restrict__ out,
                      int nrows)
{
    extern __shared__ float smem[];
    float* xs  = smem;              // [22272]
    float* hkd = smem + XS_FLOATS;  // [2][5696]

    const int tid  = threadIdx.x;
    const int row0 = blockIdx.x * 2;
    const int nr   = (nrows - row0 >= 2) ? 2 : (nrows - row0); // rows handled here

    // ---------------- Phase 1: load x rows into smem ----------------
    {
        const float4* src = (const float4*)(x + (size_t)row0 * D_DIM);
        float4* dst = (float4*)xs;
        const int n4 = nr * (D_DIM / 4);
        for (int i = tid; i < n4; i += THREADS) dst[i] = src[i];
        // zero any unloaded region + pad (j-padding reads must be 0, not NaN)
        for (int i = nr * D_DIM + tid; i < XS_FLOATS; i += THREADS) xs[i] = 0.f;
    }

    // prefetch had_K tile 0 into registers (overlaps with x load latency)
    float pre[6];
    {
        #pragma unroll
        for (int q = 0; q < 6; ++q) {
            int idx = tid + q * THREADS;
            float v = 0.f;
            if (idx < K_DIM * JT) {
                int i = idx >> 4, jj = idx & 15;          // tile 0: j = jj < 172
                v = hK[i * K_DIM + jj];
            }
            pre[q] = v;
        }
    }
    __syncthreads();

    // ---------------- Phase 2: FWHT-64 per chunk (warp-cooperative) ----------------
    {
        const int w = tid >> 5, l = tid & 31;
        const float scale = rsqrtf((float)D_DIM);
        for (int c = w; c < 2 * K_DIM; c += (THREADS / 32)) {
            float* p = xs + c * 64;
            float v0 = p[l], v1 = p[l + 32];
            float t0 = v0 + v1, t1 = v0 - v1;            // stage h=32 (register)
            #pragma unroll
            for (int h = 1; h <= 16; h <<= 1) {          // stages h=1..16 (shfl)
                float w0 = __shfl_xor_sync(0xffffffffu, t0, h);
                float w1 = __shfl_xor_sync(0xffffffffu, t1, h);
                if (l & h) { t0 = w0 - t0; t1 = w1 - t1; }
                else       { t0 = t0 + w0; t1 = t1 + w1; }
            }
            p[l] = t0 * scale;
            p[l + 32] = t1 * scale;
        }
        // commit prefetched tile 0 (value-duplicated for packed FMA2 broadcast)
        float2* hw = (float2*)hkd;
        #pragma unroll
        for (int q = 0; q < 6; ++q) {
            int idx = tid + q * THREADS;
            if (idx < K_DIM * JT) {
                int i = idx >> 4, jj = idx & 15;
                hw[jj * 177 + i] = make_float2(pre[q], pre[q]);
            }
        }
    }
    __syncthreads();

    // ---------------- Phase 3: out = had_K @ Xf  (register-tiled FFMA2) ----------------
    const int row = tid >> 8;            // 0..1 : which of the 2 rows
    const int u   = tid & 255;
    const int mg  = u & 7;               // m-group: m0 = mg*8
    const int ig  = u >> 3;              // 0..31  : i0 = ig*6 (padded to 192)
    const int i0  = ig * TI;

    ull acc[TI][4];
    #pragma unroll
    for (int t = 0; t < TI; ++t)
        #pragma unroll
        for (int p = 0; p < 4; ++p) acc[t][p] = 0ull;

    const float* xrow = xs + row * D_DIM + mg * TM;

    for (int jt = 0; jt < NT; ++jt) {
        // prefetch next had_K tile (zero-padded past j=171)
        if (jt + 1 < NT) {
            const int j0n = (jt + 1) * JT;
            #pragma unroll
            for (int q = 0; q < 6; ++q) {
                int idx = tid + q * THREADS;
                float v = 0.f;
                if (idx < K_DIM * JT) {
                    int i = idx >> 4, jj = idx & 15, j = j0n + jj;
                    if (j < K_DIM) v = hK[i * K_DIM + j];
                }
                pre[q] = v;
            }
        }
        const float* hb = hkd + (jt & 1) * HK_BUF;
        const int j0 = jt * JT;
        #pragma unroll 4
        for (int jj = 0; jj < JT; ++jj) {
            const float* xp = xrow + (j0 + jj) * 64;
            ulonglong2 xa = *(const ulonglong2*)(xp);       // m0..m0+3 packed
            ulonglong2 xb = *(const ulonglong2*)(xp + 4);   // m0+4..m0+7 packed
            const float* hp = hb + jj * 354 + 2 * i0;       // duplicated scalars
            #pragma unroll
            for (int t = 0; t < TI; ++t) {
                ull h2 = *(const ull*)(hp + 2 * t);         // {h,h}
                acc[t][0] = fma2(h2, xa.x, acc[t][0]);
                acc[t][1] = fma2(h2, xa.y, acc[t][1]);
                acc[t][2] = fma2(h2, xb.x, acc[t][2]);
                acc[t][3] = fma2(h2, xb.y, acc[t][3]);
            }
        }
        // commit next tile to the other buffer
        if (jt + 1 < NT) {
            float2* hw = (float2*)(hkd + ((jt + 1) & 1) * HK_BUF);
            #pragma unroll
            for (int q = 0; q < 6; ++q) {
                int idx = tid + q * THREADS;
                if (idx < K_DIM * JT) {
                    int i = idx >> 4, jj = idx & 15;
                    hw[jj * 177 + i] = make_float2(pre[q], pre[q]);
                }
            }
        }
        __syncthreads();
    }

    // ---------------- epilogue: store ----------------
    if (row0 + row < nrows) {
        float* orow = out + (size_t)(row0 + row) * D_DIM + mg * TM;
        #pragma unroll
        for (int t = 0; t < TI; ++t) {
            int i = i0 + t;
            if (i < K_DIM) {
                ulonglong2 s0, s1;
                s0.x = acc[t][0]; s0.y = acc[t][1];
                s1.x = acc[t][2]; s1.y = acc[t][3];
                *(ulonglong2*)(orow + i * 64)     = s0;
                *(ulonglong2*)(orow + i * 64 + 4) = s1;
            }
        }
    }
}

extern "C" void kernel_launch(void* const* d_in, const int* in_sizes, int n_in,
                              void* d_out, int out_size)
{
    const float* x  = (const float*)d_in[0];
    const float* hK = (const float*)d_in[1];
    int nx = in_sizes[0];
    // defensive: identify had_K by its size (K*K) in case of input-order surprises
    if (n_in > 1 && in_sizes[0] == K_DIM * K_DIM) {
        x  = (const float*)d_in[1];
        hK = (const float*)d_in[0];
        nx = in_sizes[1];
    }
    float* out = (float*)d_out;

    const int nrows = nx / D_DIM;
    const int ncta  = (nrows + 1) / 2;
    const size_t smem = SMEM_FLOATS * sizeof(float);   // 134656 B

    cudaFuncSetAttribute(had_fused_kernel,
                         cudaFuncAttributeMaxDynamicSharedMemorySize, (int)smem);
    had_fused_kernel<<<ncta, THREADS, smem>>>(x, hK, out, nrows);
}